// round 16
// baseline (speedup 1.0000x reference)
#include <cuda_runtime.h>
#include <cuda_fp16.h>

// GaussianLayer: 2D Gaussian "same" conv (25x25, center tap zeroed) over
// src (4,512,512,21) NHWC fp32.  dst = g_y * (g_x * src) - src.
// Round 16: resubmission of round 15 (infra failure, never ran).
// Round-12 champion (78.6us) + ONE isolated change: evict-first cache hints
// (__ldcs/__stcs) on pass_v's stream-once src/dst traffic to protect
// g_tmp's L2 residency.  No launch-bounds/reg changes.

#define BATCH 4
#define HH    512
#define WW    512
#define CC    21
#define RR    12
#define TAPS  25
#define ROWF  (WW * CC)          /* 10752 floats per (b,y) row */
#define IMGF  (HH * ROWF)
#define TOTALF (BATCH * IMGF)    /* 22,020,096 */

typedef unsigned long long u64;

__device__ __half g_tmp[TOTALF];   // 44 MB fp16 scratch (L2-resident for pass_v)

__device__ __forceinline__ u64 pack2(float lo, float hi) {
    u64 r; asm("mov.b64 %0, {%1, %2};" : "=l"(r) : "f"(lo), "f"(hi)); return r;
}
__device__ __forceinline__ void fma2(u64& d, u64 a, u64 b) {
    asm("fma.rn.f32x2 %0, %1, %2, %0;" : "+l"(d) : "l"(a), "l"(b));
}
__device__ __forceinline__ float2 unpack2(u64 v) {
    float2 f; asm("mov.b64 {%0, %1}, %2;" : "=f"(f.x), "=f"(f.y) : "l"(v)); return f;
}

// 13 symmetric 1D weights from row RR of the 2D kernel; center weight = 1
// (the zeroed 2D center tap is handled by subtracting src at the end).
__device__ __forceinline__ void load_weights(const float* __restrict__ k, u64* W2) {
#pragma unroll
    for (int j = 0; j < 12; ++j) {
        float w = __ldg(k + RR * TAPS + j);
        W2[j] = pack2(w, w);
    }
    W2[12] = pack2(1.0f, 1.0f);
}

// ---------------- Pass 1: horizontal. 16 adjacent x outputs per thread, -----
// scalar sliding window of 40 front-batched loads (L1-served), FFMA2 pairs.
// (exact round-6/12 form — best measured)
__global__ void __launch_bounds__(256) pass_h_kernel(const float* __restrict__ src,
                                                     const float* __restrict__ k) {
    const int PER_ROW = (WW / 16) * CC;             // 672 threads per (b,y) row
    int tid = blockIdx.x * 256 + threadIdx.x;       // grid sized exactly

    int row = tid / PER_ROW;                        // b*HH + y
    int rem = tid - row * PER_ROW;
    int xg  = rem / CC;
    int c   = rem - xg * CC;
    int x0  = xg * 16;

    const float* rp = src   + (size_t)row * ROWF;
    __half*      op = g_tmp + (size_t)row * ROWF;
    int base = x0 * CC + c;

    u64 W2[13];
    load_weights(k, W2);

    float v[40];
    if (x0 >= RR && x0 + 27 < WW) {                 // interior: xin in range
#pragma unroll
        for (int s = 0; s < 40; ++s)
            v[s] = rp[base + (s - RR) * CC];
    } else {
#pragma unroll
        for (int s = 0; s < 40; ++s) {
            int xin = x0 - RR + s;
            v[s] = (xin >= 0 && xin < WW) ? rp[base + (s - RR) * CC] : 0.0f;
        }
    }

    // A[m] accumulates outputs (x0+2m, x0+2m+1), m = 0..7
    u64 A[8] = {0ull, 0ull, 0ull, 0ull, 0ull, 0ull, 0ull, 0ull};
#pragma unroll
    for (int i = 0; i < 39; ++i) {
        u64 P = pack2(v[i], v[i + 1]);
#pragma unroll
        for (int m = 0; m < 8; ++m) {
            int n = i - 2 * m;
            if (n >= 0 && n < TAPS)
                fma2(A[m], W2[n <= RR ? n : 24 - n], P);
        }
    }

#pragma unroll
    for (int m = 0; m < 8; ++m) {
        float2 o = unpack2(A[m]);
        op[base + (2 * m)     * CC] = __float2half_rn(o.x);
        op[base + (2 * m + 1) * CC] = __float2half_rn(o.y);
    }
}

// ---------------- Pass 2: vertical, src folded into accumulator init --------
// Thread = one half2 column pair x 8 y outputs.  Issue order: 8 src LDG.64
// first (DRAM, evict-first), then 32 tmp window loads (L2-resident), then
// A[m] = -src, fma loop, evict-first stores.
__global__ void __launch_bounds__(256) pass_v_kernel(const float* __restrict__ src,
                                                     const float* __restrict__ k,
                                                     float* __restrict__ dst) {
    const int PAIRS = ROWF / 2;                     // 5376 pairs per row
    const int PER_B = (HH / 8) * PAIRS;             // 344,064 threads per batch
    int tid = blockIdx.x * 256 + threadIdx.x;

    int b   = tid / PER_B;
    int rem = tid - b * PER_B;
    int yg  = rem / PAIRS;
    int fp  = rem - yg * PAIRS;
    int y0  = yg * 8;

    size_t off = (size_t)b * IMGF + 2 * (size_t)fp;
    const __half* tp = g_tmp + off;
    const float*  sp = src + off;
    float*        dp = dst + off;

    u64 W2[13];
    load_weights(k, W2);

    // 1) src loads first (stream-once -> evict-first; protects tmp in L2).
    float2 s2[8];
#pragma unroll
    for (int m = 0; m < 8; ++m)
        s2[m] = __ldcs((const float2*)(sp + (size_t)(y0 + m) * ROWF));

    // 2) tmp window loads (want L2 hits).
    __half2 v[32];
    if (y0 >= RR && y0 + 19 < HH) {
#pragma unroll
        for (int s = 0; s < 32; ++s)
            v[s] = *(const __half2*)(tp + (size_t)(y0 - RR + s) * ROWF);
    } else {
        const __half2 z = __float2half2_rn(0.0f);
#pragma unroll
        for (int s = 0; s < 32; ++s) {
            int yin = y0 - RR + s;
            v[s] = (yin >= 0 && yin < HH)
                       ? *(const __half2*)(tp + (size_t)yin * ROWF)
                       : z;
        }
    }

    // 3) accumulators start at -src (src regs become the A regs).
    u64 A[8];
#pragma unroll
    for (int m = 0; m < 8; ++m)
        A[m] = pack2(-s2[m].x, -s2[m].y);

    // 4) fma loop.
#pragma unroll
    for (int s = 0; s < 32; ++s) {
        float2 f = __half22float2(v[s]);
        u64 P = pack2(f.x, f.y);
#pragma unroll
        for (int m = 0; m < 8; ++m) {
            int n = s - m;
            if (n >= 0 && n < TAPS)
                fma2(A[m], W2[n <= RR ? n : 24 - n], P);
        }
    }

    // 5) evict-first stores (dst is stream-once).
#pragma unroll
    for (int m = 0; m < 8; ++m) {
        float2 o = unpack2(A[m]);
        __stcs((float2*)(dp + (size_t)(y0 + m) * ROWF), o);
    }
}

extern "C" void kernel_launch(void* const* d_in, const int* in_sizes, int n_in,
                              void* d_out, int out_size) {
    const float* src = (const float*)d_in[0];
    const float* k   = (const float*)d_in[1];
    float*       dst = (float*)d_out;

    int nthreads_h = BATCH * HH * (WW / 16) * CC;         // 1,376,256
    pass_h_kernel<<<nthreads_h / 256, 256>>>(src, k);

    int nthreads_v = BATCH * (HH / 8) * (ROWF / 2);       // 1,376,256
    pass_v_kernel<<<nthreads_v / 256, 256>>>(src, k, dst);
}

// round 17
// speedup vs baseline: 1.0679x; 1.0679x over previous
#include <cuda_runtime.h>
#include <cuda_fp16.h>

// GaussianLayer: 2D Gaussian "same" conv (25x25, center tap zeroed) over
// src (4,512,512,21) NHWC fp32.  dst = g_y * (g_x * src) - src.
// Round 17: champion + pass_v hints (validated) + two bounded changes:
//   (1) pass_v __launch_bounds__(256,4): trim exactly 1 reg (65->64) to
//       cross the 4-CTA/SM occupancy boundary (32% -> ~42%).
//   (2) pass_h src loads __ldcs: evict-first streaming so the 44MB tmp
//       being written stays L2-resident for pass_v's first rows.

#define BATCH 4
#define HH    512
#define WW    512
#define CC    21
#define RR    12
#define TAPS  25
#define ROWF  (WW * CC)          /* 10752 floats per (b,y) row */
#define IMGF  (HH * ROWF)
#define TOTALF (BATCH * IMGF)    /* 22,020,096 */

typedef unsigned long long u64;

__device__ __half g_tmp[TOTALF];   // 44 MB fp16 scratch (L2-resident for pass_v)

__device__ __forceinline__ u64 pack2(float lo, float hi) {
    u64 r; asm("mov.b64 %0, {%1, %2};" : "=l"(r) : "f"(lo), "f"(hi)); return r;
}
__device__ __forceinline__ void fma2(u64& d, u64 a, u64 b) {
    asm("fma.rn.f32x2 %0, %1, %2, %0;" : "+l"(d) : "l"(a), "l"(b));
}
__device__ __forceinline__ float2 unpack2(u64 v) {
    float2 f; asm("mov.b64 {%0, %1}, %2;" : "=f"(f.x), "=f"(f.y) : "l"(v)); return f;
}

// 13 symmetric 1D weights from row RR of the 2D kernel; center weight = 1
// (the zeroed 2D center tap is handled by subtracting src at the end).
__device__ __forceinline__ void load_weights(const float* __restrict__ k, u64* W2) {
#pragma unroll
    for (int j = 0; j < 12; ++j) {
        float w = __ldg(k + RR * TAPS + j);
        W2[j] = pack2(w, w);
    }
    W2[12] = pack2(1.0f, 1.0f);
}

// ---------------- Pass 1: horizontal. 16 adjacent x outputs per thread, -----
// scalar sliding window of 40 front-batched loads, FFMA2 pairs.
// src loads are evict-first (stream-once) to protect tmp's L2 residency.
__global__ void __launch_bounds__(256) pass_h_kernel(const float* __restrict__ src,
                                                     const float* __restrict__ k) {
    const int PER_ROW = (WW / 16) * CC;             // 672 threads per (b,y) row
    int tid = blockIdx.x * 256 + threadIdx.x;       // grid sized exactly

    int row = tid / PER_ROW;                        // b*HH + y
    int rem = tid - row * PER_ROW;
    int xg  = rem / CC;
    int c   = rem - xg * CC;
    int x0  = xg * 16;

    const float* rp = src   + (size_t)row * ROWF;
    __half*      op = g_tmp + (size_t)row * ROWF;
    int base = x0 * CC + c;

    u64 W2[13];
    load_weights(k, W2);

    float v[40];
    if (x0 >= RR && x0 + 27 < WW) {                 // interior: xin in range
#pragma unroll
        for (int s = 0; s < 40; ++s)
            v[s] = __ldcs(rp + base + (s - RR) * CC);
    } else {
#pragma unroll
        for (int s = 0; s < 40; ++s) {
            int xin = x0 - RR + s;
            v[s] = (xin >= 0 && xin < WW) ? __ldcs(rp + base + (s - RR) * CC) : 0.0f;
        }
    }

    // A[m] accumulates outputs (x0+2m, x0+2m+1), m = 0..7
    u64 A[8] = {0ull, 0ull, 0ull, 0ull, 0ull, 0ull, 0ull, 0ull};
#pragma unroll
    for (int i = 0; i < 39; ++i) {
        u64 P = pack2(v[i], v[i + 1]);
#pragma unroll
        for (int m = 0; m < 8; ++m) {
            int n = i - 2 * m;
            if (n >= 0 && n < TAPS)
                fma2(A[m], W2[n <= RR ? n : 24 - n], P);
        }
    }

#pragma unroll
    for (int m = 0; m < 8; ++m) {
        float2 o = unpack2(A[m]);
        op[base + (2 * m)     * CC] = __float2half_rn(o.x);
        op[base + (2 * m + 1) * CC] = __float2half_rn(o.y);
    }
}

// ---------------- Pass 2: vertical, src folded into accumulator init --------
// Thread = one half2 column pair x 8 y outputs.  8 src LDG.64 first
// (evict-first), then 32 tmp window loads (L2), A[m] = -src, fma loop,
// evict-first stores.  launch_bounds(256,4): cap at 64 regs -> 4 CTAs/SM.
__global__ void __launch_bounds__(256, 4) pass_v_kernel(const float* __restrict__ src,
                                                        const float* __restrict__ k,
                                                        float* __restrict__ dst) {
    const int PAIRS = ROWF / 2;                     // 5376 pairs per row
    const int PER_B = (HH / 8) * PAIRS;             // 344,064 threads per batch
    int tid = blockIdx.x * 256 + threadIdx.x;

    int b   = tid / PER_B;
    int rem = tid - b * PER_B;
    int yg  = rem / PAIRS;
    int fp  = rem - yg * PAIRS;
    int y0  = yg * 8;

    size_t off = (size_t)b * IMGF + 2 * (size_t)fp;
    const __half* tp = g_tmp + off;
    const float*  sp = src + off;
    float*        dp = dst + off;

    u64 W2[13];
    load_weights(k, W2);

    // 1) src loads first (stream-once -> evict-first).
    float2 s2[8];
#pragma unroll
    for (int m = 0; m < 8; ++m)
        s2[m] = __ldcs((const float2*)(sp + (size_t)(y0 + m) * ROWF));

    // 2) tmp window loads (want L2 hits).
    __half2 v[32];
    if (y0 >= RR && y0 + 19 < HH) {
#pragma unroll
        for (int s = 0; s < 32; ++s)
            v[s] = *(const __half2*)(tp + (size_t)(y0 - RR + s) * ROWF);
    } else {
        const __half2 z = __float2half2_rn(0.0f);
#pragma unroll
        for (int s = 0; s < 32; ++s) {
            int yin = y0 - RR + s;
            v[s] = (yin >= 0 && yin < HH)
                       ? *(const __half2*)(tp + (size_t)yin * ROWF)
                       : z;
        }
    }

    // 3) accumulators start at -src (src regs become the A regs).
    u64 A[8];
#pragma unroll
    for (int m = 0; m < 8; ++m)
        A[m] = pack2(-s2[m].x, -s2[m].y);

    // 4) fma loop.
#pragma unroll
    for (int s = 0; s < 32; ++s) {
        float2 f = __half22float2(v[s]);
        u64 P = pack2(f.x, f.y);
#pragma unroll
        for (int m = 0; m < 8; ++m) {
            int n = s - m;
            if (n >= 0 && n < TAPS)
                fma2(A[m], W2[n <= RR ? n : 24 - n], P);
        }
    }

    // 5) evict-first stores (dst is stream-once).
#pragma unroll
    for (int m = 0; m < 8; ++m) {
        float2 o = unpack2(A[m]);
        __stcs((float2*)(dp + (size_t)(y0 + m) * ROWF), o);
    }
}

extern "C" void kernel_launch(void* const* d_in, const int* in_sizes, int n_in,
                              void* d_out, int out_size) {
    const float* src = (const float*)d_in[0];
    const float* k   = (const float*)d_in[1];
    float*       dst = (float*)d_out;

    int nthreads_h = BATCH * HH * (WW / 16) * CC;         // 1,376,256
    pass_h_kernel<<<nthreads_h / 256, 256>>>(src, k);

    int nthreads_v = BATCH * (HH / 8) * (ROWF / 2);       // 1,376,256
    pass_v_kernel<<<nthreads_v / 256, 256>>>(src, k, dst);
}